// round 7
// baseline (speedup 1.0000x reference)
#include <cuda_runtime.h>

#define BB 2
#define NN 384
#define HID 512
#define RD 256
#define R2 128
#define R4 64
#define NH 8
#define ROWS (BB*NN)              // 768
#define TJ 32
#define TILES (ROWS*(NN/TJ))      // 9216

// ---------------- scratch ----------------
__device__ float g_q[ROWS*RD];
__device__ float g_k[ROWS*RD];
__device__ float g_v[ROWS*HID];
__device__ float g_att[(size_t)ROWS*NN*NH];
__device__ float g_out1p[4][ROWS*HID];

__device__ __forceinline__ float warp_sum(float v){
  #pragma unroll
  for (int o=16;o;o>>=1) v += __shfl_xor_sync(0xffffffffu, v, o);
  return v;
}
typedef unsigned long long ull;
__device__ __forceinline__ ull fma2(ull a, ull b, ull c){
  ull d;
  asm("fma.rn.f32x2 %0, %1, %2, %3;" : "=l"(d) : "l"(a), "l"(b), "l"(c));
  return d;
}
__device__ __forceinline__ ull pack2(float x){
  ull d;
  asm("mov.b64 %0, {%1, %1};" : "=l"(d) : "f"(x));
  return d;
}
__device__ __forceinline__ float lo2(ull v){ return __uint_as_float((unsigned)v); }
__device__ __forceinline__ float hi2(ull v){ return __uint_as_float((unsigned)(v>>32)); }

#define BAR_OG() asm volatile("bar.sync %0, 128;" :: "r"(og+1) : "memory")

// dummy kernel to keep the ncu capture slot on kB
__global__ void kNop(){}

// ---------------- kernel A ----------------
__global__ void __launch_bounds__(256) kA(const float* __restrict__ node,
    const float* __restrict__ g0, const float* __restrict__ b0,
    const float* __restrict__ Wq, const float* __restrict__ bq,
    const float* __restrict__ Wk, const float* __restrict__ bk,
    const float* __restrict__ Wv, const float* __restrict__ bv)
{
  __shared__ float xs[8][HID];
  int tid = threadIdx.x, w = tid>>5, lane = tid&31;
  int r0 = blockIdx.x*8;
  {
    const float* np = node + (size_t)(r0+w)*HID;
    float vals[16]; float s=0.f, q2=0.f;
    #pragma unroll
    for (int u=0;u<16;++u){ float v = np[lane+32*u]; vals[u]=v; s+=v; q2+=v*v; }
    s = warp_sum(s); q2 = warp_sum(q2);
    float m = s*(1.f/HID);
    float rstd = rsqrtf(q2*(1.f/HID) - m*m + 1e-5f);
    #pragma unroll
    for (int u=0;u<16;++u){ int c = lane+32*u; xs[w][c] = fmaxf((vals[u]-m)*rstd*g0[c]+b0[c], 0.f); }
  }
  __syncthreads();
  float aq[8], ak[8], av0[8], av1[8];
  #pragma unroll
  for (int rr=0;rr<8;++rr){aq[rr]=0.f;ak[rr]=0.f;av0[rr]=0.f;av1[rr]=0.f;}
  #pragma unroll 4
  for (int h=0; h<HID; ++h){
    float wq = Wq[h*RD+tid], wk = Wk[h*RD+tid];
    float wv0 = Wv[h*HID+tid], wv1 = Wv[h*HID+tid+256];
    #pragma unroll
    for (int rr=0;rr<8;++rr){
      float x = xs[rr][h];
      aq[rr] += x*wq; ak[rr] += x*wk; av0[rr] += x*wv0; av1[rr] += x*wv1;
    }
  }
  #pragma unroll
  for (int rr=0;rr<8;++rr){
    g_q[(r0+rr)*RD+tid]  = aq[rr]+bq[tid];
    g_k[(r0+rr)*RD+tid]  = ak[rr]+bk[tid];
    g_v[(r0+rr)*HID+tid]      = av0[rr]+bv[tid];
    g_v[(r0+rr)*HID+tid+256]  = av1[rr]+bv[tid+256];
  }
}

// ---------------- kernel B: pair-MLP; 4 og x 4 ksplit, named barriers ----------------
#define NTB 512
__global__ void __launch_bounds__(512) kB(
    const float* __restrict__ edge, const float* __restrict__ lrel_in,
    const int* __restrict__ drctn, const float* __restrict__ rmask,
    const float* __restrict__ ln1g, const float* __restrict__ ln1b,
    const float* __restrict__ W1, const float* __restrict__ b1,
    const float* __restrict__ ln2g, const float* __restrict__ ln2b,
    const float* __restrict__ W2, const float* __restrict__ b2,
    const float* __restrict__ dirW,
    const float* __restrict__ ln3g, const float* __restrict__ ln3b,
    const float* __restrict__ W3, const float* __restrict__ b3,
    float* __restrict__ lrel_out)
{
  extern __shared__ float sm[];
  float* W1s = sm;                 // 32768
  float* W2s = W1s + 32768;        // 8192
  float* W3s = W2s + 8192;         // 512
  float* dirs = W3s + 512;         // 768
  float* l1g = dirs + 768;         // 256
  float* l1b = l1g + 256;          // 256
  float* b1s = l1b + 256;          // 128
  float* l2g = b1s + 128;          // 128
  float* l2b = l2g + 128;          // 128
  float* b2s = l2b + 128;          // 64
  float* l3g = b2s + 64;           // 64
  float* l3b = l3g + 64;           // 64
  float* b3s = l3b + 64;           // 8
  float* qs  = b3s + 8;            // 256
  int*   dj  = (int*)(qs + 256);   // 64 (32 used)
  float* rel = (float*)(dj + 64);  // 8192
  float* h1  = rel + 8192;         // 4096
  // total 55992 floats = 223968 B

  int tid = threadIdx.x;
  for (int i=tid; i<32768; i+=NTB) W1s[i]=W1[i];
  for (int i=tid; i<8192;  i+=NTB) W2s[i]=W2[i];
  for (int i=tid; i<512;   i+=NTB) W3s[i]=W3[i];
  for (int i=tid; i<768;   i+=NTB) dirs[i]=dirW[i];
  if (tid<256){ l1g[tid]=ln1g[tid]; l1b[tid]=ln1b[tid]; }
  if (tid<128){ b1s[tid]=b1[tid]; l2g[tid]=ln2g[tid]; l2b[tid]=ln2b[tid]; }
  if (tid<64){  b2s[tid]=b2[tid]; l3g[tid]=ln3g[tid]; l3b[tid]=ln3b[tid]; }
  if (tid<8)    b3s[tid]=b3[tid];

  int w = tid>>5, lane = tid&31;
  int og = w>>2, ks = w&3;             // 4 output groups x 4 K-splits

  for (int tl = blockIdx.x; tl < TILES; tl += gridDim.x){
    int bi = tl/(NN/TJ);
    int j0 = (tl%(NN/TJ))*TJ;
    int brow = (bi/NN)*NN;

    // stage next-tile params (buffers not read since many syncs ago)
    if (tid<256) qs[tid] = g_q[bi*RD+tid];
    if (tid<TJ) dj[tid] = drctn[(size_t)bi*NN + j0 + tid];
    float rm_pf = 0.f;
    size_t ib_pf = 0;
    if (tid < 256){
      int t = tid>>3, hh = tid&7;
      ib_pf = ((size_t)bi*NN + j0 + t)*NH + hh;
      rm_pf = rmask[ib_pf];
    }
    __syncthreads();                   // (1) covers smem reuse + qs/dj

    // phase 1: rel = q_i * k_j + edge + dir_emb[d]
    {
      int half = tid>>8, c = tid&255;
      float qv = qs[c];
      const float* kp = g_k + (size_t)(brow + j0 + half*16)*RD + c;
      const float* ep = edge + ((size_t)bi*NN + j0 + half*16)*RD + c;
      float* rp = rel + (half*16)*RD + c;
      #pragma unroll 4
      for (int t0=0;t0<16;++t0){
        float kv = kp[(size_t)t0*RD];
        float ev = ep[(size_t)t0*RD];
        float dv = dirs[dj[half*16+t0]*RD + c];
        rp[t0*RD] = qv*kv + ev + dv;
      }
    }
    // L2 prefetch for NEXT tile's DRAM operands (consumed ~10K cyc later)
    {
      int tl2 = tl + gridDim.x;
      if (tl2 < TILES){
        int bi2 = tl2/(NN/TJ);
        int j02 = (tl2%(NN/TJ))*TJ;
        if (tid < 256){
          const char* eb = (const char*)(edge + ((size_t)bi2*NN + j02)*RD);
          asm volatile("prefetch.global.L2 [%0];" :: "l"(eb + (size_t)tid*128));
        } else if (tid < 320){
          const char* lb = (const char*)(lrel_in + ((size_t)bi2*NN + j02)*R4);
          asm volatile("prefetch.global.L2 [%0];" :: "l"(lb + (size_t)(tid-256)*128));
        } else if (tid < 328){
          const char* rb2 = (const char*)(rmask + ((size_t)bi2*NN + j02)*NH);
          asm volatile("prefetch.global.L2 [%0];" :: "l"(rb2 + (size_t)(tid-320)*128));
        }
      }
    }
    __syncthreads();                   // (2) rel ready

    // LN1 fused: warp w owns pairs 2w, 2w+1 (og-local for GEMM1)
    #pragma unroll
    for (int p=0;p<2;++p){
      int t = 2*w+p;
      float v[8]; float s=0.f,q2=0.f;
      #pragma unroll
      for (int u=0;u<8;++u){ v[u] = rel[t*RD + lane+32*u]; s+=v[u]; q2+=v[u]*v[u]; }
      s=warp_sum(s); q2=warp_sum(q2);
      float m = s*(1.f/RD);
      float rstd = rsqrtf(q2*(1.f/RD)-m*m+1e-5f);
      #pragma unroll
      for (int u=0;u<8;++u){
        int r = lane+32*u;
        rel[t*RD + r] = (v[u]-m)*rstd*l1g[r]+l1b[r];
      }
    }
    BAR_OG();

    // GEMM1: warp tile = 8 pairs x 128 cols, 4-way split-K
    {
      ull acc[8][2];
      #pragma unroll
      for (int p=0;p<8;++p){ acc[p][0]=0ull; acc[p][1]=0ull; }
      const int rbase = ks*64;
      const float* rp = rel + (8*og)*RD;
      #pragma unroll 1
      for (int rb=rbase; rb<rbase+64; rb+=4){
        float a4[8][4];
        #pragma unroll
        for (int p=0;p<8;++p) *(float4*)a4[p] = *(const float4*)(rp + p*RD + rb);
        #pragma unroll
        for (int k=0;k<4;++k){
          ulonglong2 wv = *(const ulonglong2*)(W1s + (rb+k)*R2 + 4*lane);
          #pragma unroll
          for (int p=0;p<8;++p){
            ull a = pack2(a4[p][k]);
            acc[p][0] = fma2(a, wv.x, acc[p][0]);
            acc[p][1] = fma2(a, wv.y, acc[p][1]);
          }
        }
      }
      BAR_OG();                        // og's warps done reading rel slice
      float* scr1 = rel + og*2048;
      float* scr2 = rel + og*2048 + 1024;
      float* scr3 = h1  + og*1024;
      if (ks==1){
        #pragma unroll
        for (int p=0;p<8;++p){ ulonglong2 v; v.x=acc[p][0]; v.y=acc[p][1];
          *(ulonglong2*)(scr1 + p*128 + 4*lane) = v; }
      } else if (ks==2){
        #pragma unroll
        for (int p=0;p<8;++p){ ulonglong2 v; v.x=acc[p][0]; v.y=acc[p][1];
          *(ulonglong2*)(scr2 + p*128 + 4*lane) = v; }
      } else if (ks==3){
        #pragma unroll
        for (int p=0;p<8;++p){ ulonglong2 v; v.x=acc[p][0]; v.y=acc[p][1];
          *(ulonglong2*)(scr3 + p*128 + 4*lane) = v; }
      }
      BAR_OG();
      if (ks==0){
        int c0 = 4*lane;
        #pragma unroll
        for (int p=0;p<8;++p){
          float4 q1 = *(const float4*)(scr1 + p*128 + c0);
          float4 q2 = *(const float4*)(scr2 + p*128 + c0);
          float4 q3 = *(const float4*)(scr3 + p*128 + c0);
          float4 o;
          o.x = fmaxf(lo2(acc[p][0])+q1.x+q2.x+q3.x+b1s[c0  ],0.f);
          o.y = fmaxf(hi2(acc[p][0])+q1.y+q2.y+q3.y+b1s[c0+1],0.f);
          o.z = fmaxf(lo2(acc[p][1])+q1.z+q2.z+q3.z+b1s[c0+2],0.f);
          o.w = fmaxf(hi2(acc[p][1])+q1.w+q2.w+q3.w+b1s[c0+3],0.f);
          *(float4*)(h1 + (8*og+p)*R2 + c0) = o;
        }
      }
      BAR_OG();
    }

    // LN2 fused: warp w owns pairs 2w, 2w+1 (og-local)
    #pragma unroll
    for (int p=0;p<2;++p){
      int t=2*w+p;
      float v[4]; float s=0.f,q2=0.f;
      #pragma unroll
      for (int u=0;u<4;++u){ v[u]=h1[t*R2+lane+32*u]; s+=v[u]; q2+=v[u]*v[u]; }
      s=warp_sum(s); q2=warp_sum(q2);
      float m = s*(1.f/R2);
      float rstd = rsqrtf(q2*(1.f/R2)-m*m+1e-5f);
      #pragma unroll
      for (int u=0;u<4;++u){
        int r = lane+32*u;
        h1[t*R2+r]=(v[u]-m)*rstd*l2g[r]+l2b[r];
      }
    }
    BAR_OG();

    // GEMM2: warp tile = 8 pairs x 64 cols, 4-way split-K; + last_relation
    float* lr = rel;                   // [0:2048) final last_rel tile
    {
      ull acc[8];
      #pragma unroll
      for (int p=0;p<8;++p) acc[p]=0ull;
      const int rbase = ks*32;
      const float* hp = h1 + (8*og)*R2;
      #pragma unroll 1
      for (int rb=rbase; rb<rbase+32; rb+=4){
        float a4[8][4];
        #pragma unroll
        for (int p=0;p<8;++p) *(float4*)a4[p] = *(const float4*)(hp + p*R2 + rb);
        #pragma unroll
        for (int k=0;k<4;++k){
          ull wv = *(const ull*)(W2s + (rb+k)*R4 + 2*lane);
          #pragma unroll
          for (int p=0;p<8;++p) acc[p] = fma2(pack2(a4[p][k]), wv, acc[p]);
        }
      }
      BAR_OG();                        // og's warps done reading h1 slice
      float* s1 = h1 + og*1024;
      float* s2 = h1 + og*1024 + 512;
      float* s3 = rel + 4096 + og*512;
      if (ks==1){
        #pragma unroll
        for (int p=0;p<8;++p) *(ull*)(s1 + p*64 + 2*lane) = acc[p];
      } else if (ks==2){
        #pragma unroll
        for (int p=0;p<8;++p) *(ull*)(s2 + p*64 + 2*lane) = acc[p];
      } else if (ks==3){
        #pragma unroll
        for (int p=0;p<8;++p) *(ull*)(s3 + p*64 + 2*lane) = acc[p];
      }
      BAR_OG();
      if (ks==0){
        int c0 = 2*lane;
        #pragma unroll
        for (int p=0;p<8;++p){
          int t = 8*og+p;
          float2 q1 = *(const float2*)(s1 + p*64 + c0);
          float2 q2 = *(const float2*)(s2 + p*64 + c0);
          float2 q3 = *(const float2*)(s3 + p*64 + c0);
          size_t base = ((size_t)bi*NN + j0 + t)*R4 + c0;
          float2 lrin = *(const float2*)(lrel_in + base);
          float2 o;
          o.x = lo2(acc[p])+q1.x+q2.x+q3.x+b2s[c0  ]+lrin.x;
          o.y = hi2(acc[p])+q1.y+q2.y+q3.y+b2s[c0+1]+lrin.y;
          *(float2*)(lrel_out + base) = o;
          lr[t*R4+c0]=o.x; lr[t*R4+c0+1]=o.y;
        }
      }
    }
    __syncthreads();                   // (3) lr complete; h1 free (a3 spans og slices)

    // LN3 fused on relu(last_rel): writes a3 = h1 region, pad 65 (conflict-free GEMM3)
    float* a3 = h1;                    // 32*65 = 2080 <= 4096
    #pragma unroll
    for (int p=0;p<2;++p){
      int t=2*w+p;
      float v0=fmaxf(lr[t*R4+lane],0.f), v1=fmaxf(lr[t*R4+lane+32],0.f);
      float s=warp_sum(v0+v1), q2=warp_sum(v0*v0+v1*v1);
      float m = s*(1.f/R4);
      float rstd = rsqrtf(q2*(1.f/R4)-m*m+1e-5f);
      a3[t*65+lane]    = (v0-m)*rstd*l3g[lane]+l3b[lane];
      a3[t*65+lane+32] = (v1-m)*rstd*l3g[lane+32]+l3b[lane+32];
    }
    __syncthreads();                   // (4) a3 ready for cross-og GEMM3

    // GEMM3 partials: warp w covers k in [4w,4w+4), lane = pair
    ull* p3 = (ull*)(rel + 4096);      // 4 head-pair regions x 512 ull
    {
      ull acc0=0,acc1=0,acc2=0,acc3=0;
      #pragma unroll
      for (int u=0;u<4;++u){
        int k = w*4+u;
        ull a2 = pack2(a3[lane*65 + k]);
        ulonglong2 w01 = *(const ulonglong2*)(W3s + k*NH);
        ulonglong2 w23 = *(const ulonglong2*)(W3s + k*NH + 4);
        acc0=fma2(a2,w01.x,acc0); acc1=fma2(a2,w01.y,acc1);
        acc2=fma2(a2,w23.x,acc2); acc3=fma2(a2,w23.y,acc3);
      }
      p3[0*512 + w*32 + lane]=acc0;    // heads 0,1
      p3[1*512 + w*32 + lane]=acc1;    // heads 2,3
      p3[2*512 + w*32 + lane]=acc2;    // heads 4,5
      p3[3*512 + w*32 + lane]=acc3;    // heads 6,7
    }
    __syncthreads();                   // (5)
    if (tid < 256){
      int t = tid>>3, hh = tid&7;
      const float* scrf = rel + 4096;
      float acc=0.f;
      #pragma unroll
      for (int u=0;u<16;++u) acc += scrf[(hh>>1)*1024 + (u*32+t)*2 + (hh&1)];
      g_att[ib_pf] = acc + b3s[hh] + rm_pf;
    }
  }
}

// ---------------- kernel C: softmax over j ----------------
__global__ void __launch_bounds__(256) kC()
{
  __shared__ float s[NN*NH];
  int bi = blockIdx.x, tid=threadIdx.x;
  float* g = g_att + (size_t)bi*NN*NH;
  for (int i=tid;i<NN*NH;i+=256) s[i]=g[i];
  __syncthreads();
  int w=tid>>5, lane=tid&31;
  float mx=-3.4e38f;
  float e[12];
  #pragma unroll
  for (int u=0;u<12;++u) mx = fmaxf(mx, s[(lane+32*u)*NH + w]);
  #pragma unroll
  for (int o=16;o;o>>=1) mx = fmaxf(mx, __shfl_xor_sync(0xffffffffu,mx,o));
  float sum=0.f;
  #pragma unroll
  for (int u=0;u<12;++u){ e[u]=__expf(s[(lane+32*u)*NH+w]-mx); sum+=e[u]; }
  sum = warp_sum(sum);
  float inv = 1.f/sum;
  #pragma unroll
  for (int u=0;u<12;++u) s[(lane+32*u)*NH+w] = e[u]*inv;
  __syncthreads();
  for (int i=tid;i<NN*NH;i+=256) g[i]=s[i];
}

// ---------------- kernel D: partial attn*V over j-splits ----------------
__global__ void __launch_bounds__(256) kD()
{
  __shared__ float as[4][32*NH];
  int tid=threadIdx.x;
  int row0 = blockIdx.x*4;
  int js = blockIdx.y;
  int b = row0/NN;
  int h0 = tid>>6;
  float acc0[4], acc1[4];
  #pragma unroll
  for (int rr=0;rr<4;++rr){acc0[rr]=0.f;acc1[rr]=0.f;}
  for (int jc=0;jc<3;++jc){
    int jb = js*96 + jc*32;
    __syncthreads();
    for (int idx=tid; idx<4*32*NH; idx+=256){
      int rr=idx>>8, rest=idx&255;
      as[rr][rest] = g_att[((size_t)(row0+rr)*NN + jb)*NH + rest];
    }
    __syncthreads();
    #pragma unroll 4
    for (int jj=0;jj<32;++jj){
      const float* vp = g_v + (size_t)(b*NN + jb+jj)*HID;
      float v0=vp[tid], v1=vp[tid+256];
      #pragma unroll
      for (int rr=0;rr<4;++rr){
        acc0[rr]+=as[rr][jj*NH+h0]*v0;
        acc1[rr]+=as[rr][jj*NH+h0+4]*v1;
      }
    }
  }
  #pragma unroll
  for (int rr=0;rr<4;++rr){
    g_out1p[js][(row0+rr)*HID + tid]     = acc0[rr];
    g_out1p[js][(row0+rr)*HID + tid+256] = acc1[rr];
  }
}

// ---------------- kernel E ----------------
__global__ void __launch_bounds__(256) kE(const float* __restrict__ Wo,
                                          const float* __restrict__ bo,
                                          float* __restrict__ out)
{
  __shared__ float ys[8][HID];
  int tid=threadIdx.x; int r0=blockIdx.x*8;
  for (int idx=tid; idx<8*HID; idx+=256){
    size_t base=(size_t)r0*HID+idx;
    ys[idx>>9][idx&511] = g_out1p[0][base]+g_out1p[1][base]+g_out1p[2][base]+g_out1p[3][base];
  }
  __syncthreads();
  float a0[8],a1[8];
  #pragma unroll
  for (int rr=0;rr<8;++rr){a0[rr]=0.f;a1[rr]=0.f;}
  #pragma unroll 4
  for (int h=0;h<HID;++h){
    float w0=Wo[h*HID+tid], w1=Wo[h*HID+tid+256];
    #pragma unroll
    for (int rr=0;rr<8;++rr){ float x=ys[rr][h]; a0[rr]+=x*w0; a1[rr]+=x*w1; }
  }
  #pragma unroll
  for (int rr=0;rr<8;++rr){
    out[(r0+rr)*HID+tid]     = a0[rr]+bo[tid];
    out[(r0+rr)*HID+tid+256] = a1[rr]+bo[tid+256];
  }
}

// ---------------- launch ----------------
extern "C" void kernel_launch(void* const* d_in, const int* in_sizes, int n_in,
                              void* d_out, int out_size)
{
  const float* node        = (const float*)d_in[0];
  const float* edge        = (const float*)d_in[1];
  const float* last_rel_in = (const float*)d_in[2];
  const int* drctn         = (const int*)d_in[3];
  const float* rel_mask    = (const float*)d_in[4];
  const float* ln0_g=(const float*)d_in[5];  const float* ln0_b=(const float*)d_in[6];
  const float* Wq=(const float*)d_in[7];     const float* bq=(const float*)d_in[8];
  const float* Wk=(const float*)d_in[9];     const float* bk=(const float*)d_in[10];
  const float* Wv=(const float*)d_in[11];    const float* bv=(const float*)d_in[12];
  const float* ln1_g=(const float*)d_in[13]; const float* ln1_b=(const float*)d_in[14];
  const float* W1=(const float*)d_in[15];    const float* b1=(const float*)d_in[16];
  const float* ln2_g=(const float*)d_in[17]; const float* ln2_b=(const float*)d_in[18];
  const float* W2=(const float*)d_in[19];    const float* b2=(const float*)d_in[20];
  const float* dir_emb=(const float*)d_in[21];
  const float* ln3_g=(const float*)d_in[22]; const float* ln3_b=(const float*)d_in[23];
  const float* W3=(const float*)d_in[24];    const float* b3=(const float*)d_in[25];
  const float* Wo=(const float*)d_in[26];    const float* bo=(const float*)d_in[27];

  float* out = (float*)d_out;
  const size_t LRELN = (size_t)BB*NN*NN*R4;
  float* lrel_out = out + ((size_t)out_size - LRELN);

  kNop<<<1,32>>>();
  kNop<<<1,32>>>();

  kA<<<ROWS/8,256>>>(node, ln0_g, ln0_b, Wq,bq,Wk,bk,Wv,bv);

  const int SMEM_B = 55992*4;
  cudaFuncSetAttribute(kB, cudaFuncAttributeMaxDynamicSharedMemorySize, SMEM_B);
  kB<<<152,512,SMEM_B>>>(edge, last_rel_in, drctn, rel_mask,
                         ln1_g, ln1_b, W1, b1, ln2_g, ln2_b, W2, b2,
                         dir_emb, ln3_g, ln3_b, W3, b3, lrel_out);

  kC<<<ROWS,256>>>();
  kD<<<dim3(192,4),256>>>();
  kE<<<ROWS/8,256>>>(Wo, bo, out);
}

// round 8
// speedup vs baseline: 1.5003x; 1.5003x over previous
#include <cuda_runtime.h>

#define BB 2
#define NN 384
#define HID 512
#define RD 256
#define R2 128
#define R4 64
#define NH 8
#define ROWS (BB*NN)              // 768
#define TJ 32
#define TILES (ROWS*(NN/TJ))      // 9216

// ---------------- scratch ----------------
__device__ float g_q[ROWS*RD];
__device__ float g_k[ROWS*RD];
__device__ float g_v[ROWS*HID];
__device__ float g_att[(size_t)ROWS*NN*NH];
__device__ float g_out1p[4][ROWS*HID];

__device__ __forceinline__ float warp_sum(float v){
  #pragma unroll
  for (int o=16;o;o>>=1) v += __shfl_xor_sync(0xffffffffu, v, o);
  return v;
}
typedef unsigned long long ull;
__device__ __forceinline__ ull fma2(ull a, ull b, ull c){
  ull d;
  asm("fma.rn.f32x2 %0, %1, %2, %3;" : "=l"(d) : "l"(a), "l"(b), "l"(c));
  return d;
}
__device__ __forceinline__ ull pack2(float x){
  ull d;
  asm("mov.b64 %0, {%1, %1};" : "=l"(d) : "f"(x));
  return d;
}
__device__ __forceinline__ float lo2(ull v){ return __uint_as_float((unsigned)v); }
__device__ __forceinline__ float hi2(ull v){ return __uint_as_float((unsigned)(v>>32)); }

// dummy kernel to keep the ncu capture slot on kB
__global__ void kNop(){}

// ---------------- kernel A ----------------
__global__ void __launch_bounds__(256) kA(const float* __restrict__ node,
    const float* __restrict__ g0, const float* __restrict__ b0,
    const float* __restrict__ Wq, const float* __restrict__ bq,
    const float* __restrict__ Wk, const float* __restrict__ bk,
    const float* __restrict__ Wv, const float* __restrict__ bv)
{
  __shared__ float xs[8][HID];
  int tid = threadIdx.x, w = tid>>5, lane = tid&31;
  int r0 = blockIdx.x*8;
  {
    const float* np = node + (size_t)(r0+w)*HID;
    float vals[16]; float s=0.f, q2=0.f;
    #pragma unroll
    for (int u=0;u<16;++u){ float v = np[lane+32*u]; vals[u]=v; s+=v; q2+=v*v; }
    s = warp_sum(s); q2 = warp_sum(q2);
    float m = s*(1.f/HID);
    float rstd = rsqrtf(q2*(1.f/HID) - m*m + 1e-5f);
    #pragma unroll
    for (int u=0;u<16;++u){ int c = lane+32*u; xs[w][c] = fmaxf((vals[u]-m)*rstd*g0[c]+b0[c], 0.f); }
  }
  __syncthreads();
  float aq[8], ak[8], av0[8], av1[8];
  #pragma unroll
  for (int rr=0;rr<8;++rr){aq[rr]=0.f;ak[rr]=0.f;av0[rr]=0.f;av1[rr]=0.f;}
  #pragma unroll 4
  for (int h=0; h<HID; ++h){
    float wq = Wq[h*RD+tid], wk = Wk[h*RD+tid];
    float wv0 = Wv[h*HID+tid], wv1 = Wv[h*HID+tid+256];
    #pragma unroll
    for (int rr=0;rr<8;++rr){
      float x = xs[rr][h];
      aq[rr] += x*wq; ak[rr] += x*wk; av0[rr] += x*wv0; av1[rr] += x*wv1;
    }
  }
  #pragma unroll
  for (int rr=0;rr<8;++rr){
    g_q[(r0+rr)*RD+tid]  = aq[rr]+bq[tid];
    g_k[(r0+rr)*RD+tid]  = ak[rr]+bk[tid];
    g_v[(r0+rr)*HID+tid]      = av0[rr]+bv[tid];
    g_v[(r0+rr)*HID+tid+256]  = av1[rr]+bv[tid+256];
  }
}

// ---------------- kernel B: pair-MLP (R6 structure, GEMM3 conflict fixes) ----------------
#define NTB 512
__global__ void __launch_bounds__(512) kB(
    const float* __restrict__ edge, const float* __restrict__ lrel_in,
    const int* __restrict__ drctn, const float* __restrict__ rmask,
    const float* __restrict__ ln1g, const float* __restrict__ ln1b,
    const float* __restrict__ W1, const float* __restrict__ b1,
    const float* __restrict__ ln2g, const float* __restrict__ ln2b,
    const float* __restrict__ W2, const float* __restrict__ b2,
    const float* __restrict__ dirW,
    const float* __restrict__ ln3g, const float* __restrict__ ln3b,
    const float* __restrict__ W3, const float* __restrict__ b3,
    float* __restrict__ lrel_out)
{
  extern __shared__ float sm[];
  float* W1s = sm;                 // 32768
  float* W2s = W1s + 32768;        // 8192
  float* W3s = W2s + 8192;         // 512
  float* dirs = W3s + 512;         // 768
  float* l1g = dirs + 768;         // 256
  float* l1b = l1g + 256;          // 256
  float* b1s = l1b + 256;          // 128
  float* l2g = b1s + 128;          // 128
  float* l2b = l2g + 128;          // 128
  float* b2s = l2b + 128;          // 64
  float* l3g = b2s + 64;           // 64
  float* l3b = l3g + 64;           // 64
  float* b3s = l3b + 64;           // 8
  float* qs  = b3s + 8;            // 256
  int*   dj  = (int*)(qs + 256);   // 64 (32 used)
  float* rel = (float*)(dj + 64);  // 8192 (later: lr[0:2048], scratch[4096:8192])
  float* h1  = rel + 8192;         // 4096 (later: a3 padded 32*65=2080)
  // total 55992 floats = 223968 B

  int tid = threadIdx.x;
  for (int i=tid; i<32768; i+=NTB) W1s[i]=W1[i];
  for (int i=tid; i<8192;  i+=NTB) W2s[i]=W2[i];
  for (int i=tid; i<512;   i+=NTB) W3s[i]=W3[i];
  for (int i=tid; i<768;   i+=NTB) dirs[i]=dirW[i];
  if (tid<256){ l1g[tid]=ln1g[tid]; l1b[tid]=ln1b[tid]; }
  if (tid<128){ b1s[tid]=b1[tid]; l2g[tid]=ln2g[tid]; l2b[tid]=ln2b[tid]; }
  if (tid<64){  b2s[tid]=b2[tid]; l3g[tid]=ln3g[tid]; l3b[tid]=ln3b[tid]; }
  if (tid<8)    b3s[tid]=b3[tid];

  int w = tid>>5, lane = tid&31;
  int og = w>>1, ks = w&1;             // 8 output groups x 2 K-splits

  for (int tl = blockIdx.x; tl < TILES; tl += gridDim.x){
    int bi = tl/(NN/TJ);
    int j0 = (tl%(NN/TJ))*TJ;
    int brow = (bi/NN)*NN;
    __syncthreads();                   // (1) protects smem reuse across tiles

    if (tid<256) qs[tid] = g_q[bi*RD+tid];
    if (tid<TJ) dj[tid] = drctn[(size_t)bi*NN + j0 + tid];

    // prefetch DRAM operands consumed in late phases
    float2 lrin_pf[4];
    if (ks==0){
      #pragma unroll
      for (int p=0;p<4;++p){
        size_t base = ((size_t)bi*NN + j0 + 4*og + p)*R4 + 2*lane;
        lrin_pf[p] = *(const float2*)(lrel_in + base);
      }
    }
    float rm_pf = 0.f;
    size_t ib_pf = 0;
    if (tid < 256){
      int t = tid>>3, hh = tid&7;
      ib_pf = ((size_t)bi*NN + j0 + t)*NH + hh;
      rm_pf = rmask[ib_pf];
    }
    __syncthreads();                   // (2)

    // phase 1: rel = q_i * k_j + edge + dir_emb[d]
    {
      int half = tid>>8, c = tid&255;
      float qv = qs[c];
      const float* kp = g_k + (size_t)(brow + j0 + half*16)*RD + c;
      const float* ep = edge + ((size_t)bi*NN + j0 + half*16)*RD + c;
      float* rp = rel + (half*16)*RD + c;
      #pragma unroll 4
      for (int t0=0;t0<16;++t0){
        float kv = kp[(size_t)t0*RD];
        float ev = ep[(size_t)t0*RD];
        float dv = dirs[dj[half*16+t0]*RD + c];
        rp[t0*RD] = qv*kv + ev + dv;
      }
    }
    __syncthreads();                   // (3) rel ready

    // LN1 fused: warp w owns pairs 2w, 2w+1
    #pragma unroll
    for (int p=0;p<2;++p){
      int t = 2*w+p;
      float v[8]; float s=0.f,q2=0.f;
      #pragma unroll
      for (int u=0;u<8;++u){ v[u] = rel[t*RD + lane+32*u]; s+=v[u]; q2+=v[u]*v[u]; }
      s=warp_sum(s); q2=warp_sum(q2);
      float m = s*(1.f/RD);
      float rstd = rsqrtf(q2*(1.f/RD)-m*m+1e-5f);
      #pragma unroll
      for (int u=0;u<8;++u){
        int r = lane+32*u;
        rel[t*RD + r] = (v[u]-m)*rstd*l1g[r]+l1b[r];
      }
    }
    __syncthreads();                   // (4)

    // GEMM1: h1 = relu(LNrel @ W1 + b1). warp tile = 4 pairs x 128 cols, split-K (ks).
    {
      ull acc[4][2];
      #pragma unroll
      for (int p=0;p<4;++p){ acc[p][0]=0ull; acc[p][1]=0ull; }
      int rbase = ks*128;
      const float* rp = rel + (4*og)*RD;
      #pragma unroll 2
      for (int rb=rbase; rb<rbase+128; rb+=4){
        float a4[4][4];
        #pragma unroll
        for (int p=0;p<4;++p) *(float4*)a4[p] = *(const float4*)(rp + p*RD + rb);
        #pragma unroll
        for (int k=0;k<4;++k){
          ulonglong2 wv = *(const ulonglong2*)(W1s + (rb+k)*R2 + 4*lane);
          #pragma unroll
          for (int p=0;p<4;++p){
            ull a = pack2(a4[p][k]);
            acc[p][0] = fma2(a, wv.x, acc[p][0]);
            acc[p][1] = fma2(a, wv.y, acc[p][1]);
          }
        }
      }
      if (ks==1){
        #pragma unroll
        for (int p=0;p<4;++p){
          ulonglong2 v; v.x=acc[p][0]; v.y=acc[p][1];
          *(ulonglong2*)(h1 + (4*og+p)*R2 + 4*lane) = v;
        }
      }
      __syncthreads();                 // (5)
      if (ks==0){
        int c0=4*lane;
        #pragma unroll
        for (int p=0;p<4;++p){
          int t=4*og+p;
          float4 part = *(const float4*)(h1 + t*R2 + c0);
          float4 o;
          o.x=fmaxf(lo2(acc[p][0])+part.x+b1s[c0  ],0.f);
          o.y=fmaxf(hi2(acc[p][0])+part.y+b1s[c0+1],0.f);
          o.z=fmaxf(lo2(acc[p][1])+part.z+b1s[c0+2],0.f);
          o.w=fmaxf(hi2(acc[p][1])+part.w+b1s[c0+3],0.f);
          *(float4*)(h1 + t*R2 + c0) = o;
        }
      }
    }
    __syncthreads();                   // (6)

    // LN2 fused: warp w owns pairs 2w, 2w+1
    #pragma unroll
    for (int p=0;p<2;++p){
      int t=2*w+p;
      float v[4]; float s=0.f,q2=0.f;
      #pragma unroll
      for (int u=0;u<4;++u){ v[u]=h1[t*R2+lane+32*u]; s+=v[u]; q2+=v[u]*v[u]; }
      s=warp_sum(s); q2=warp_sum(q2);
      float m = s*(1.f/R2);
      float rstd = rsqrtf(q2*(1.f/R2)-m*m+1e-5f);
      #pragma unroll
      for (int u=0;u<4;++u){
        int r = lane+32*u;
        h1[t*R2+r]=(v[u]-m)*rstd*l2g[r]+l2b[r];
      }
    }
    __syncthreads();                   // (7)

    // GEMM2 + add last_relation; warp tile = 4 pairs x 64 cols, split-K.
    float* lr  = rel;            // [0,2048)
    float* g2s = rel + 4096;     // [4096,6144) partials
    {
      ull acc[4];
      #pragma unroll
      for (int p=0;p<4;++p) acc[p]=0ull;
      int rbase = ks*64;
      const float* hp = h1 + (4*og)*R2;
      #pragma unroll 2
      for (int rb=rbase; rb<rbase+64; rb+=4){
        float a4[4][4];
        #pragma unroll
        for (int p=0;p<4;++p) *(float4*)a4[p] = *(const float4*)(hp + p*R2 + rb);
        #pragma unroll
        for (int k=0;k<4;++k){
          ull wv = *(const ull*)(W2s + (rb+k)*R4 + 2*lane);
          #pragma unroll
          for (int p=0;p<4;++p) acc[p] = fma2(pack2(a4[p][k]), wv, acc[p]);
        }
      }
      if (ks==1){
        #pragma unroll
        for (int p=0;p<4;++p)
          *(ull*)(g2s + (4*og+p)*R4 + 2*lane) = acc[p];
      }
      __syncthreads();                 // (8)
      if (ks==0){
        int c0=2*lane;
        #pragma unroll
        for (int p=0;p<4;++p){
          int t=4*og+p;
          ull part = *(const ull*)(g2s + t*R4 + c0);
          size_t base = ((size_t)bi*NN + j0 + t)*R4 + c0;
          float2 o;
          o.x = lo2(acc[p])+lo2(part)+b2s[c0]  +lrin_pf[p].x;
          o.y = hi2(acc[p])+hi2(part)+b2s[c0+1]+lrin_pf[p].y;
          *(float2*)(lrel_out + base) = o;
          lr[t*R4+c0]=o.x; lr[t*R4+c0+1]=o.y;
        }
      }
    }
    __syncthreads();                   // (9) lr complete; h1 free

    // LN3 fused on relu(last_rel): writes a3 into h1 region, stride-65 pad
    // (conflict-free GEMM3 reads: bank = (lane*65+k)&31 = (lane+k)&31, all distinct)
    float* a3 = h1;                    // 32*65 = 2080 <= 4096
    #pragma unroll
    for (int p=0;p<2;++p){
      int t=2*w+p;
      float v0=fmaxf(lr[t*R4+lane],0.f), v1=fmaxf(lr[t*R4+lane+32],0.f);
      float s=warp_sum(v0+v1), q2=warp_sum(v0*v0+v1*v1);
      float m = s*(1.f/R4);
      float rstd = rsqrtf(q2*(1.f/R4)-m*m+1e-5f);
      a3[t*65+lane]    = (v0-m)*rstd*l3g[lane]+l3b[lane];
      a3[t*65+lane+32] = (v1-m)*rstd*l3g[lane+32]+l3b[lane+32];
    }
    __syncthreads();                   // (10) a3 ready

    // GEMM3 partials: warp w covers k in [4w,4w+4), lane = pair; conflict-free stores
    ull* p3 = (ull*)(rel + 4096);      // 4 head-pair regions x 512 ull
    {
      ull acc0=0,acc1=0,acc2=0,acc3=0;
      #pragma unroll
      for (int u=0;u<4;++u){
        int k = w*4+u;
        ull a2 = pack2(a3[lane*65 + k]);
        ulonglong2 w01 = *(const ulonglong2*)(W3s + k*NH);
        ulonglong2 w23 = *(const ulonglong2*)(W3s + k*NH + 4);
        acc0=fma2(a2,w01.x,acc0); acc1=fma2(a2,w01.y,acc1);
        acc2=fma2(a2,w23.x,acc2); acc3=fma2(a2,w23.y,acc3);
      }
      p3[0*512 + w*32 + lane]=acc0;    // heads 0,1
      p3[1*512 + w*32 + lane]=acc1;    // heads 2,3
      p3[2*512 + w*32 + lane]=acc2;    // heads 4,5
      p3[3*512 + w*32 + lane]=acc3;    // heads 6,7
    }
    __syncthreads();                   // (11)
    if (tid < 256){
      int t = tid>>3, hh = tid&7;
      const float* scrf = rel + 4096;
      float acc=0.f;
      #pragma unroll
      for (int u=0;u<16;++u) acc += scrf[(hh>>1)*1024 + (u*32+t)*2 + (hh&1)];
      g_att[ib_pf] = acc + b3s[hh] + rm_pf;
    }
  }
}

// ---------------- kernel C: softmax over j ----------------
__global__ void __launch_bounds__(256) kC()
{
  __shared__ float s[NN*NH];
  int bi = blockIdx.x, tid=threadIdx.x;
  float* g = g_att + (size_t)bi*NN*NH;
  for (int i=tid;i<NN*NH;i+=256) s[i]=g[i];
  __syncthreads();
  int w=tid>>5, lane=tid&31;
  float mx=-3.4e38f;
  float e[12];
  #pragma unroll
  for (int u=0;u<12;++u) mx = fmaxf(mx, s[(lane+32*u)*NH + w]);
  #pragma unroll
  for (int o=16;o;o>>=1) mx = fmaxf(mx, __shfl_xor_sync(0xffffffffu,mx,o));
  float sum=0.f;
  #pragma unroll
  for (int u=0;u<12;++u){ e[u]=__expf(s[(lane+32*u)*NH+w]-mx); sum+=e[u]; }
  sum = warp_sum(sum);
  float inv = 1.f/sum;
  #pragma unroll
  for (int u=0;u<12;++u) s[(lane+32*u)*NH+w] = e[u]*inv;
  __syncthreads();
  for (int i=tid;i<NN*NH;i+=256) g[i]=s[i];
}

// ---------------- kernel D: partial attn*V over j-splits ----------------
__global__ void __launch_bounds__(256) kD()
{
  __shared__ float as[4][32*NH];
  int tid=threadIdx.x;
  int row0 = blockIdx.x*4;
  int js = blockIdx.y;
  int b = row0/NN;
  int h0 = tid>>6;
  float acc0[4], acc1[4];
  #pragma unroll
  for (int rr=0;rr<4;++rr){acc0[rr]=0.f;acc1[rr]=0.f;}
  for (int jc=0;jc<3;++jc){
    int jb = js*96 + jc*32;
    __syncthreads();
    for (int idx=tid; idx<4*32*NH; idx+=256){
      int rr=idx>>8, rest=idx&255;
      as[rr][rest] = g_att[((size_t)(row0+rr)*NN + jb)*NH + rest];
    }
    __syncthreads();
    #pragma unroll 4
    for (int jj=0;jj<32;++jj){
      const float* vp = g_v + (size_t)(b*NN + jb+jj)*HID;
      float v0=vp[tid], v1=vp[tid+256];
      #pragma unroll
      for (int rr=0;rr<4;++rr){
        acc0[rr]+=as[rr][jj*NH+h0]*v0;
        acc1[rr]+=as[rr][jj*NH+h0+4]*v1;
      }
    }
  }
  #pragma unroll
  for (int rr=0;rr<4;++rr){
    g_out1p[js][(row0+rr)*HID + tid]     = acc0[rr];
    g_out1p[js][(row0+rr)*HID + tid+256] = acc1[rr];
  }
}

// ---------------- kernel E ----------------
__global__ void __launch_bounds__(256) kE(const float* __restrict__ Wo,
                                          const float* __restrict__ bo,
                                          float* __restrict__ out)
{
  __shared__ float ys[8][HID];
  int tid=threadIdx.x; int r0=blockIdx.x*8;
  for (int idx=tid; idx<8*HID; idx+=256){
    size_t base=(size_t)r0*HID+idx;
    ys[idx>>9][idx&511] = g_out1p[0][base]+g_out1p[1][base]+g_out1p[2][base]+g_out1p[3][base];
  }
  __syncthreads();
  float a0[8],a1[8];
  #pragma unroll
  for (int rr=0;rr<8;++rr){a0[rr]=0.f;a1[rr]=0.f;}
  #pragma unroll 4
  for (int h=0;h<HID;++h){
    float w0=Wo[h*HID+tid], w1=Wo[h*HID+tid+256];
    #pragma unroll
    for (int rr=0;rr<8;++rr){ float x=ys[rr][h]; a0[rr]+=x*w0; a1[rr]+=x*w1; }
  }
  #pragma unroll
  for (int rr=0;rr<8;++rr){
    out[(r0+rr)*HID+tid]     = a0[rr]+bo[tid];
    out[(r0+rr)*HID+tid+256] = a1[rr]+bo[tid+256];
  }
}

// ---------------- launch ----------------
extern "C" void kernel_launch(void* const* d_in, const int* in_sizes, int n_in,
                              void* d_out, int out_size)
{
  const float* node        = (const float*)d_in[0];
  const float* edge        = (const float*)d_in[1];
  const float* last_rel_in = (const float*)d_in[2];
  const int* drctn         = (const int*)d_in[3];
  const float* rel_mask    = (const float*)d_in[4];
  const float* ln0_g=(const float*)d_in[5];  const float* ln0_b=(const float*)d_in[6];
  const float* Wq=(const float*)d_in[7];     const float* bq=(const float*)d_in[8];
  const float* Wk=(const float*)d_in[9];     const float* bk=(const float*)d_in[10];
  const float* Wv=(const float*)d_in[11];    const float* bv=(const float*)d_in[12];
  const float* ln1_g=(const float*)d_in[13]; const float* ln1_b=(const float*)d_in[14];
  const float* W1=(const float*)d_in[15];    const float* b1=(const float*)d_in[16];
  const float* ln2_g=(const float*)d_in[17]; const float* ln2_b=(const float*)d_in[18];
  const float* W2=(const float*)d_in[19];    const float* b2=(const float*)d_in[20];
  const float* dir_emb=(const float*)d_in[21];
  const float* ln3_g=(const float*)d_in[22]; const float* ln3_b=(const float*)d_in[23];
  const float* W3=(const float*)d_in[24];    const float* b3=(const float*)d_in[25];
  const float* Wo=(const float*)d_in[26];    const float* bo=(const float*)d_in[27];

  float* out = (float*)d_out;
  const size_t LRELN = (size_t)BB*NN*NN*R4;
  float* lrel_out = out + ((size_t)out_size - LRELN);

  kNop<<<1,32>>>();
  kNop<<<1,32>>>();

  kA<<<ROWS/8,256>>>(node, ln0_g, ln0_b, Wq,bq,Wk,bk,Wv,bv);

  const int SMEM_B = 55992*4;
  cudaFuncSetAttribute(kB, cudaFuncAttributeMaxDynamicSharedMemorySize, SMEM_B);
  kB<<<152,512,SMEM_B>>>(edge, last_rel_in, drctn, rel_mask,
                         ln1_g, ln1_b, W1, b1, ln2_g, ln2_b, W2, b2,
                         dir_emb, ln3_g, ln3_b, W3, b3, lrel_out);

  kC<<<ROWS,256>>>();
  kD<<<dim3(192,4),256>>>();
  kE<<<ROWS/8,256>>>(Wo, bo, out);
}

// round 9
// speedup vs baseline: 1.5133x; 1.0087x over previous
#include <cuda_runtime.h>

#define BB 2
#define NN 384
#define HID 512
#define RD 256
#define R2 128
#define R4 64
#define NH 8
#define ROWS (BB*NN)              // 768
#define TJ 32
#define TILES (ROWS*(NN/TJ))      // 9216

// ---------------- scratch ----------------
__device__ float g_q[ROWS*RD];
__device__ float g_k[ROWS*RD];
__device__ float g_v[ROWS*HID];
__device__ float g_att[(size_t)ROWS*NN*NH];
__device__ float g_out1p[4][ROWS*HID];

__device__ __forceinline__ float warp_sum(float v){
  #pragma unroll
  for (int o=16;o;o>>=1) v += __shfl_xor_sync(0xffffffffu, v, o);
  return v;
}
typedef unsigned long long ull;
__device__ __forceinline__ ull fma2(ull a, ull b, ull c){
  ull d;
  asm("fma.rn.f32x2 %0, %1, %2, %3;" : "=l"(d) : "l"(a), "l"(b), "l"(c));
  return d;
}
__device__ __forceinline__ ull pack2(float x){
  ull d;
  asm("mov.b64 %0, {%1, %1};" : "=l"(d) : "f"(x));
  return d;
}
__device__ __forceinline__ float lo2(ull v){ return __uint_as_float((unsigned)v); }
__device__ __forceinline__ float hi2(ull v){ return __uint_as_float((unsigned)(v>>32)); }

// dummy kernel to keep the ncu capture slot on kB
__global__ void kNop(){}

// ---------------- kernel A ----------------
__global__ void __launch_bounds__(256) kA(const float* __restrict__ node,
    const float* __restrict__ g0, const float* __restrict__ b0,
    const float* __restrict__ Wq, const float* __restrict__ bq,
    const float* __restrict__ Wk, const float* __restrict__ bk,
    const float* __restrict__ Wv, const float* __restrict__ bv)
{
  __shared__ float xs[8][HID];
  int tid = threadIdx.x, w = tid>>5, lane = tid&31;
  int r0 = blockIdx.x*8;
  {
    const float* np = node + (size_t)(r0+w)*HID;
    float vals[16]; float s=0.f, q2=0.f;
    #pragma unroll
    for (int u=0;u<16;++u){ float v = np[lane+32*u]; vals[u]=v; s+=v; q2+=v*v; }
    s = warp_sum(s); q2 = warp_sum(q2);
    float m = s*(1.f/HID);
    float rstd = rsqrtf(q2*(1.f/HID) - m*m + 1e-5f);
    #pragma unroll
    for (int u=0;u<16;++u){ int c = lane+32*u; xs[w][c] = fmaxf((vals[u]-m)*rstd*g0[c]+b0[c], 0.f); }
  }
  __syncthreads();
  float aq[8], ak[8], av0[8], av1[8];
  #pragma unroll
  for (int rr=0;rr<8;++rr){aq[rr]=0.f;ak[rr]=0.f;av0[rr]=0.f;av1[rr]=0.f;}
  #pragma unroll 4
  for (int h=0; h<HID; ++h){
    float wq = Wq[h*RD+tid], wk = Wk[h*RD+tid];
    float wv0 = Wv[h*HID+tid], wv1 = Wv[h*HID+tid+256];
    #pragma unroll
    for (int rr=0;rr<8;++rr){
      float x = xs[rr][h];
      aq[rr] += x*wq; ak[rr] += x*wk; av0[rr] += x*wv0; av1[rr] += x*wv1;
    }
  }
  #pragma unroll
  for (int rr=0;rr<8;++rr){
    g_q[(r0+rr)*RD+tid]  = aq[rr]+bq[tid];
    g_k[(r0+rr)*RD+tid]  = ak[rr]+bk[tid];
    g_v[(r0+rr)*HID+tid]      = av0[rr]+bv[tid];
    g_v[(r0+rr)*HID+tid+256]  = av1[rr]+bv[tid+256];
  }
}

// ---------------- kernel B: pair-MLP; P=8 pairs/warp, 4-way split-K, plain syncs ----------------
#define NTB 512
__global__ void __launch_bounds__(512) kB(
    const float* __restrict__ edge, const float* __restrict__ lrel_in,
    const int* __restrict__ drctn, const float* __restrict__ rmask,
    const float* __restrict__ ln1g, const float* __restrict__ ln1b,
    const float* __restrict__ W1, const float* __restrict__ b1,
    const float* __restrict__ ln2g, const float* __restrict__ ln2b,
    const float* __restrict__ W2, const float* __restrict__ b2,
    const float* __restrict__ dirW,
    const float* __restrict__ ln3g, const float* __restrict__ ln3b,
    const float* __restrict__ W3, const float* __restrict__ b3,
    float* __restrict__ lrel_out)
{
  extern __shared__ float sm[];
  float* W1s = sm;                 // 32768
  float* W2s = W1s + 32768;        // 8192
  float* W3s = W2s + 8192;         // 512
  float* dirs = W3s + 512;         // 768
  float* l1g = dirs + 768;         // 256
  float* l1b = l1g + 256;          // 256
  float* b1s = l1b + 256;          // 128
  float* l2g = b1s + 128;          // 128
  float* l2b = l2g + 128;          // 128
  float* b2s = l2b + 128;          // 64
  float* l3g = b2s + 64;           // 64
  float* l3b = l3g + 64;           // 64
  float* b3s = l3b + 64;           // 8
  float* qs  = b3s + 8;            // 256
  int*   dj  = (int*)(qs + 256);   // 64 (32 used)
  float* rel = (float*)(dj + 64);  // 8192
  float* h1  = rel + 8192;         // 4096
  // total 55992 floats = 223968 B

  int tid = threadIdx.x;
  for (int i=tid; i<32768; i+=NTB) W1s[i]=W1[i];
  for (int i=tid; i<8192;  i+=NTB) W2s[i]=W2[i];
  for (int i=tid; i<512;   i+=NTB) W3s[i]=W3[i];
  for (int i=tid; i<768;   i+=NTB) dirs[i]=dirW[i];
  if (tid<256){ l1g[tid]=ln1g[tid]; l1b[tid]=ln1b[tid]; }
  if (tid<128){ b1s[tid]=b1[tid]; l2g[tid]=ln2g[tid]; l2b[tid]=ln2b[tid]; }
  if (tid<64){  b2s[tid]=b2[tid]; l3g[tid]=ln3g[tid]; l3b[tid]=ln3b[tid]; }
  if (tid<8)    b3s[tid]=b3[tid];

  int w = tid>>5, lane = tid&31;
  int og = w>>2, ks = w&3;             // 4 output groups x 4 K-splits

  for (int tl = blockIdx.x; tl < TILES; tl += gridDim.x){
    int bi = tl/(NN/TJ);
    int j0 = (tl%(NN/TJ))*TJ;
    int brow = (bi/NN)*NN;
    __syncthreads();                   // (1) protects smem reuse across tiles

    if (tid<256) qs[tid] = g_q[bi*RD+tid];
    if (tid<TJ) dj[tid] = drctn[(size_t)bi*NN + j0 + tid];

    // prefetch DRAM operands consumed in late phases (ks==0 warps finalize GEMM2)
    float2 lrin_pf[8];
    if (ks==0){
      #pragma unroll
      for (int p=0;p<8;++p){
        size_t base = ((size_t)bi*NN + j0 + 8*og + p)*R4 + 2*lane;
        lrin_pf[p] = *(const float2*)(lrel_in + base);
      }
    }
    float rm_pf = 0.f;
    size_t ib_pf = 0;
    if (tid < 256){
      int t = tid>>3, hh = tid&7;
      ib_pf = ((size_t)bi*NN + j0 + t)*NH + hh;
      rm_pf = rmask[ib_pf];
    }
    __syncthreads();                   // (2)

    // phase 1: rel = q_i * k_j + edge + dir_emb[d]
    {
      int half = tid>>8, c = tid&255;
      float qv = qs[c];
      const float* kp = g_k + (size_t)(brow + j0 + half*16)*RD + c;
      const float* ep = edge + ((size_t)bi*NN + j0 + half*16)*RD + c;
      float* rp = rel + (half*16)*RD + c;
      #pragma unroll 4
      for (int t0=0;t0<16;++t0){
        float kv = kp[(size_t)t0*RD];
        float ev = ep[(size_t)t0*RD];
        float dv = dirs[dj[half*16+t0]*RD + c];
        rp[t0*RD] = qv*kv + ev + dv;
      }
    }
    __syncthreads();                   // (3) rel ready

    // LN1 fused: warp w owns pairs 2w, 2w+1
    #pragma unroll
    for (int p=0;p<2;++p){
      int t = 2*w+p;
      float v[8]; float s=0.f,q2=0.f;
      #pragma unroll
      for (int u=0;u<8;++u){ v[u] = rel[t*RD + lane+32*u]; s+=v[u]; q2+=v[u]*v[u]; }
      s=warp_sum(s); q2=warp_sum(q2);
      float m = s*(1.f/RD);
      float rstd = rsqrtf(q2*(1.f/RD)-m*m+1e-5f);
      #pragma unroll
      for (int u=0;u<8;++u){
        int r = lane+32*u;
        rel[t*RD + r] = (v[u]-m)*rstd*l1g[r]+l1b[r];
      }
    }
    __syncthreads();                   // (4)

    // GEMM1: h1 = relu(LNrel @ W1 + b1). warp tile = 8 pairs x 128 cols, 4-way split-K.
    {
      ull acc[8][2];
      #pragma unroll
      for (int p=0;p<8;++p){ acc[p][0]=0ull; acc[p][1]=0ull; }
      const int rbase = ks*64;
      const float* rp = rel + (8*og)*RD;
      #pragma unroll 2
      for (int rb=rbase; rb<rbase+64; rb+=4){
        float a4[8][4];
        #pragma unroll
        for (int p=0;p<8;++p) *(float4*)a4[p] = *(const float4*)(rp + p*RD + rb);
        #pragma unroll
        for (int k=0;k<4;++k){
          ulonglong2 wv = *(const ulonglong2*)(W1s + (rb+k)*R2 + 4*lane);
          #pragma unroll
          for (int p=0;p<8;++p){
            ull a = pack2(a4[p][k]);
            acc[p][0] = fma2(a, wv.x, acc[p][0]);
            acc[p][1] = fma2(a, wv.y, acc[p][1]);
          }
        }
      }
      __syncthreads();                 // (5) all warps done reading rel -> rel reusable
      // publish partials: ks1 -> rel[og*2048], ks2 -> rel[og*2048+1024], ks3 -> h1[og*1024]
      if (ks==1){
        #pragma unroll
        for (int p=0;p<8;++p){ ulonglong2 v; v.x=acc[p][0]; v.y=acc[p][1];
          *(ulonglong2*)(rel + og*2048 + p*128 + 4*lane) = v; }
      } else if (ks==2){
        #pragma unroll
        for (int p=0;p<8;++p){ ulonglong2 v; v.x=acc[p][0]; v.y=acc[p][1];
          *(ulonglong2*)(rel + og*2048 + 1024 + p*128 + 4*lane) = v; }
      } else if (ks==3){
        #pragma unroll
        for (int p=0;p<8;++p){ ulonglong2 v; v.x=acc[p][0]; v.y=acc[p][1];
          *(ulonglong2*)(h1 + og*1024 + p*128 + 4*lane) = v; }
      }
      __syncthreads();                 // (6)
      if (ks==0){
        int c0=4*lane;
        #pragma unroll
        for (int p=0;p<8;++p){
          float4 q1 = *(const float4*)(rel + og*2048 + p*128 + c0);
          float4 q2 = *(const float4*)(rel + og*2048 + 1024 + p*128 + c0);
          float4 q3 = *(const float4*)(h1 + og*1024 + p*128 + c0);
          float4 o;
          o.x=fmaxf(lo2(acc[p][0])+q1.x+q2.x+q3.x+b1s[c0  ],0.f);
          o.y=fmaxf(hi2(acc[p][0])+q1.y+q2.y+q3.y+b1s[c0+1],0.f);
          o.z=fmaxf(lo2(acc[p][1])+q1.z+q2.z+q3.z+b1s[c0+2],0.f);
          o.w=fmaxf(hi2(acc[p][1])+q1.w+q2.w+q3.w+b1s[c0+3],0.f);
          *(float4*)(h1 + (8*og+p)*R2 + c0) = o;   // overwrites q3 slot after read
        }
      }
    }
    __syncthreads();                   // (7) h1 ready

    // LN2 fused: warp w owns pairs 2w, 2w+1
    #pragma unroll
    for (int p=0;p<2;++p){
      int t=2*w+p;
      float v[4]; float s=0.f,q2=0.f;
      #pragma unroll
      for (int u=0;u<4;++u){ v[u]=h1[t*R2+lane+32*u]; s+=v[u]; q2+=v[u]*v[u]; }
      s=warp_sum(s); q2=warp_sum(q2);
      float m = s*(1.f/R2);
      float rstd = rsqrtf(q2*(1.f/R2)-m*m+1e-5f);
      #pragma unroll
      for (int u=0;u<4;++u){
        int r = lane+32*u;
        h1[t*R2+r]=(v[u]-m)*rstd*l2g[r]+l2b[r];
      }
    }
    __syncthreads();                   // (8)

    // GEMM2 + add last_relation; warp tile = 8 pairs x 64 cols, 4-way split-K.
    float* lr = rel;                   // [0,2048) final last_rel tile
    {
      ull acc[8];
      #pragma unroll
      for (int p=0;p<8;++p) acc[p]=0ull;
      const int rbase = ks*32;
      const float* hp = h1 + (8*og)*R2;
      #pragma unroll 2
      for (int rb=rbase; rb<rbase+32; rb+=4){
        float a4[8][4];
        #pragma unroll
        for (int p=0;p<8;++p) *(float4*)a4[p] = *(const float4*)(hp + p*R2 + rb);
        #pragma unroll
        for (int k=0;k<4;++k){
          ull wv = *(const ull*)(W2s + (rb+k)*R4 + 2*lane);
          #pragma unroll
          for (int p=0;p<8;++p) acc[p] = fma2(pack2(a4[p][k]), wv, acc[p]);
        }
      }
      __syncthreads();                 // (9) all warps done reading h1 -> h1 reusable
      // publish: ks1 -> h1[og*512], ks2 -> h1[2048+og*512], ks3 -> rel[4096+og*512]
      if (ks==1){
        #pragma unroll
        for (int p=0;p<8;++p) *(ull*)(h1 + og*512 + p*64 + 2*lane) = acc[p];
      } else if (ks==2){
        #pragma unroll
        for (int p=0;p<8;++p) *(ull*)(h1 + 2048 + og*512 + p*64 + 2*lane) = acc[p];
      } else if (ks==3){
        #pragma unroll
        for (int p=0;p<8;++p) *(ull*)(rel + 4096 + og*512 + p*64 + 2*lane) = acc[p];
      }
      __syncthreads();                 // (10)
      if (ks==0){
        int c0=2*lane;
        #pragma unroll
        for (int p=0;p<8;++p){
          int t=8*og+p;
          float2 q1 = *(const float2*)(h1 + og*512 + p*64 + c0);
          float2 q2 = *(const float2*)(h1 + 2048 + og*512 + p*64 + c0);
          float2 q3 = *(const float2*)(rel + 4096 + og*512 + p*64 + c0);
          size_t base = ((size_t)bi*NN + j0 + t)*R4 + c0;
          float2 o;
          o.x = lo2(acc[p])+q1.x+q2.x+q3.x+b2s[c0  ]+lrin_pf[p].x;
          o.y = hi2(acc[p])+q1.y+q2.y+q3.y+b2s[c0+1]+lrin_pf[p].y;
          *(float2*)(lrel_out + base) = o;
          lr[t*R4+c0]=o.x; lr[t*R4+c0+1]=o.y;
        }
      }
    }
    __syncthreads();                   // (11) lr complete; h1 free

    // LN3 fused on relu(last_rel): writes a3 into h1 region, stride-65 pad
    float* a3 = h1;                    // 32*65 = 2080 <= 4096
    #pragma unroll
    for (int p=0;p<2;++p){
      int t=2*w+p;
      float v0=fmaxf(lr[t*R4+lane],0.f), v1=fmaxf(lr[t*R4+lane+32],0.f);
      float s=warp_sum(v0+v1), q2=warp_sum(v0*v0+v1*v1);
      float m = s*(1.f/R4);
      float rstd = rsqrtf(q2*(1.f/R4)-m*m+1e-5f);
      a3[t*65+lane]    = (v0-m)*rstd*l3g[lane]+l3b[lane];
      a3[t*65+lane+32] = (v1-m)*rstd*l3g[lane+32]+l3b[lane+32];
    }
    __syncthreads();                   // (12) a3 ready

    // GEMM3 partials: warp w covers k in [4w,4w+4), lane = pair; conflict-free
    ull* p3 = (ull*)(rel + 4096);      // 4 head-pair regions x 512 ull
    {
      ull acc0=0,acc1=0,acc2=0,acc3=0;
      #pragma unroll
      for (int u=0;u<4;++u){
        int k = w*4+u;
        ull a2 = pack2(a3[lane*65 + k]);
        ulonglong2 w01 = *(const ulonglong2*)(W3s + k*NH);
        ulonglong2 w23 = *(const ulonglong2*)(W3s + k*NH + 4);
        acc0=fma2(a2,w01.x,acc0); acc1=fma2(a2,w01.y,acc1);
        acc2=fma2(a2,w23.x,acc2); acc3=fma2(a2,w23.y,acc3);
      }
      p3[0*512 + w*32 + lane]=acc0;    // heads 0,1
      p3[1*512 + w*32 + lane]=acc1;    // heads 2,3
      p3[2*512 + w*32 + lane]=acc2;    // heads 4,5
      p3[3*512 + w*32 + lane]=acc3;    // heads 6,7
    }
    __syncthreads();                   // (13)
    if (tid < 256){
      int t = tid>>3, hh = tid&7;
      const float* scrf = rel + 4096;
      float acc=0.f;
      #pragma unroll
      for (int u=0;u<16;++u) acc += scrf[(hh>>1)*1024 + (u*32+t)*2 + (hh&1)];
      g_att[ib_pf] = acc + b3s[hh] + rm_pf;
    }
  }
}

// ---------------- kernel C: softmax over j ----------------
__global__ void __launch_bounds__(256) kC()
{
  __shared__ float s[NN*NH];
  int bi = blockIdx.x, tid=threadIdx.x;
  float* g = g_att + (size_t)bi*NN*NH;
  for (int i=tid;i<NN*NH;i+=256) s[i]=g[i];
  __syncthreads();
  int w=tid>>5, lane=tid&31;
  float mx=-3.4e38f;
  float e[12];
  #pragma unroll
  for (int u=0;u<12;++u) mx = fmaxf(mx, s[(lane+32*u)*NH + w]);
  #pragma unroll
  for (int o=16;o;o>>=1) mx = fmaxf(mx, __shfl_xor_sync(0xffffffffu,mx,o));
  float sum=0.f;
  #pragma unroll
  for (int u=0;u<12;++u){ e[u]=__expf(s[(lane+32*u)*NH+w]-mx); sum+=e[u]; }
  sum = warp_sum(sum);
  float inv = 1.f/sum;
  #pragma unroll
  for (int u=0;u<12;++u) s[(lane+32*u)*NH+w] = e[u]*inv;
  __syncthreads();
  for (int i=tid;i<NN*NH;i+=256) g[i]=s[i];
}

// ---------------- kernel D: partial attn*V over j-splits ----------------
__global__ void __launch_bounds__(256) kD()
{
  __shared__ float as[4][32*NH];
  int tid=threadIdx.x;
  int row0 = blockIdx.x*4;
  int js = blockIdx.y;
  int b = row0/NN;
  int h0 = tid>>6;
  float acc0[4], acc1[4];
  #pragma unroll
  for (int rr=0;rr<4;++rr){acc0[rr]=0.f;acc1[rr]=0.f;}
  for (int jc=0;jc<3;++jc){
    int jb = js*96 + jc*32;
    __syncthreads();
    for (int idx=tid; idx<4*32*NH; idx+=256){
      int rr=idx>>8, rest=idx&255;
      as[rr][rest] = g_att[((size_t)(row0+rr)*NN + jb)*NH + rest];
    }
    __syncthreads();
    #pragma unroll 4
    for (int jj=0;jj<32;++jj){
      const float* vp = g_v + (size_t)(b*NN + jb+jj)*HID;
      float v0=vp[tid], v1=vp[tid+256];
      #pragma unroll
      for (int rr=0;rr<4;++rr){
        acc0[rr]+=as[rr][jj*NH+h0]*v0;
        acc1[rr]+=as[rr][jj*NH+h0+4]*v1;
      }
    }
  }
  #pragma unroll
  for (int rr=0;rr<4;++rr){
    g_out1p[js][(row0+rr)*HID + tid]     = acc0[rr];
    g_out1p[js][(row0+rr)*HID + tid+256] = acc1[rr];
  }
}

// ---------------- kernel E ----------------
__global__ void __launch_bounds__(256) kE(const float* __restrict__ Wo,
                                          const float* __restrict__ bo,
                                          float* __restrict__ out)
{
  __shared__ float ys[8][HID];
  int tid=threadIdx.x; int r0=blockIdx.x*8;
  for (int idx=tid; idx<8*HID; idx+=256){
    size_t base=(size_t)r0*HID+idx;
    ys[idx>>9][idx&511] = g_out1p[0][base]+g_out1p[1][base]+g_out1p[2][base]+g_out1p[3][base];
  }
  __syncthreads();
  float a0[8],a1[8];
  #pragma unroll
  for (int rr=0;rr<8;++rr){a0[rr]=0.f;a1[rr]=0.f;}
  #pragma unroll 4
  for (int h=0;h<HID;++h){
    float w0=Wo[h*HID+tid], w1=Wo[h*HID+tid+256];
    #pragma unroll
    for (int rr=0;rr<8;++rr){ float x=ys[rr][h]; a0[rr]+=x*w0; a1[rr]+=x*w1; }
  }
  #pragma unroll
  for (int rr=0;rr<8;++rr){
    out[(r0+rr)*HID+tid]     = a0[rr]+bo[tid];
    out[(r0+rr)*HID+tid+256] = a1[rr]+bo[tid+256];
  }
}

// ---------------- launch ----------------
extern "C" void kernel_launch(void* const* d_in, const int* in_sizes, int n_in,
                              void* d_out, int out_size)
{
  const float* node        = (const float*)d_in[0];
  const float* edge        = (const float*)d_in[1];
  const float* last_rel_in = (const float*)d_in[2];
  const int* drctn         = (const int*)d_in[3];
  const float* rel_mask    = (const float*)d_in[4];
  const float* ln0_g=(const float*)d_in[5];  const float* ln0_b=(const float*)d_in[6];
  const float* Wq=(const float*)d_in[7];     const float* bq=(const float*)d_in[8];
  const float* Wk=(const float*)d_in[9];     const float* bk=(const float*)d_in[10];
  const float* Wv=(const float*)d_in[11];    const float* bv=(const float*)d_in[12];
  const float* ln1_g=(const float*)d_in[13]; const float* ln1_b=(const float*)d_in[14];
  const float* W1=(const float*)d_in[15];    const float* b1=(const float*)d_in[16];
  const float* ln2_g=(const float*)d_in[17]; const float* ln2_b=(const float*)d_in[18];
  const float* W2=(const float*)d_in[19];    const float* b2=(const float*)d_in[20];
  const float* dir_emb=(const float*)d_in[21];
  const float* ln3_g=(const float*)d_in[22]; const float* ln3_b=(const float*)d_in[23];
  const float* W3=(const float*)d_in[24];    const float* b3=(const float*)d_in[25];
  const float* Wo=(const float*)d_in[26];    const float* bo=(const float*)d_in[27];

  float* out = (float*)d_out;
  const size_t LRELN = (size_t)BB*NN*NN*R4;
  float* lrel_out = out + ((size_t)out_size - LRELN);

  kNop<<<1,32>>>();
  kNop<<<1,32>>>();

  kA<<<ROWS/8,256>>>(node, ln0_g, ln0_b, Wq,bq,Wk,bk,Wv,bv);

  const int SMEM_B = 55992*4;
  cudaFuncSetAttribute(kB, cudaFuncAttributeMaxDynamicSharedMemorySize, SMEM_B);
  kB<<<152,512,SMEM_B>>>(edge, last_rel_in, drctn, rel_mask,
                         ln1_g, ln1_b, W1, b1, ln2_g, ln2_b, W2, b2,
                         dir_emb, ln3_g, ln3_b, W3, b3, lrel_out);

  kC<<<ROWS,256>>>();
  kD<<<dim3(192,4),256>>>();
  kE<<<ROWS/8,256>>>(Wo, bo, out);
}

// round 10
// speedup vs baseline: 1.5571x; 1.0289x over previous
#include <cuda_runtime.h>

#define BB 2
#define NN 384
#define HID 512
#define RD 256
#define R2 128
#define R4 64
#define NH 8
#define ROWS (BB*NN)              // 768
#define TJ 32
#define TILES (ROWS*(NN/TJ))      // 9216

// ---------------- scratch ----------------
__device__ float g_q[ROWS*RD];
__device__ float g_k[ROWS*RD];
__device__ float g_v[ROWS*HID];
__device__ float g_att[(size_t)ROWS*NN*NH];
__device__ float g_out1p[4][ROWS*HID];

__device__ __forceinline__ float warp_sum(float v){
  #pragma unroll
  for (int o=16;o;o>>=1) v += __shfl_xor_sync(0xffffffffu, v, o);
  return v;
}
typedef unsigned long long ull;
__device__ __forceinline__ ull fma2(ull a, ull b, ull c){
  ull d;
  asm("fma.rn.f32x2 %0, %1, %2, %3;" : "=l"(d) : "l"(a), "l"(b), "l"(c));
  return d;
}
__device__ __forceinline__ ull pack2(float x){
  ull d;
  asm("mov.b64 %0, {%1, %1};" : "=l"(d) : "f"(x));
  return d;
}
__device__ __forceinline__ float lo2(ull v){ return __uint_as_float((unsigned)v); }
__device__ __forceinline__ float hi2(ull v){ return __uint_as_float((unsigned)(v>>32)); }

// og-local barrier: 4 warps (128 threads), ids 1..4 (0 is __syncthreads)
#define BAR_OG() asm volatile("bar.sync %0, 128;" :: "r"(og+1) : "memory")

// dummy kernel to keep the ncu capture slot on kB
__global__ void kNop(){}

// ---------------- kernel A ----------------
__global__ void __launch_bounds__(256) kA(const float* __restrict__ node,
    const float* __restrict__ g0, const float* __restrict__ b0,
    const float* __restrict__ Wq, const float* __restrict__ bq,
    const float* __restrict__ Wk, const float* __restrict__ bk,
    const float* __restrict__ Wv, const float* __restrict__ bv)
{
  __shared__ float xs[8][HID];
  int tid = threadIdx.x, w = tid>>5, lane = tid&31;
  int r0 = blockIdx.x*8;
  {
    const float* np = node + (size_t)(r0+w)*HID;
    float vals[16]; float s=0.f, q2=0.f;
    #pragma unroll
    for (int u=0;u<16;++u){ float v = np[lane+32*u]; vals[u]=v; s+=v; q2+=v*v; }
    s = warp_sum(s); q2 = warp_sum(q2);
    float m = s*(1.f/HID);
    float rstd = rsqrtf(q2*(1.f/HID) - m*m + 1e-5f);
    #pragma unroll
    for (int u=0;u<16;++u){ int c = lane+32*u; xs[w][c] = fmaxf((vals[u]-m)*rstd*g0[c]+b0[c], 0.f); }
  }
  __syncthreads();
  float aq[8], ak[8], av0[8], av1[8];
  #pragma unroll
  for (int rr=0;rr<8;++rr){aq[rr]=0.f;ak[rr]=0.f;av0[rr]=0.f;av1[rr]=0.f;}
  #pragma unroll 4
  for (int h=0; h<HID; ++h){
    float wq = Wq[h*RD+tid], wk = Wk[h*RD+tid];
    float wv0 = Wv[h*HID+tid], wv1 = Wv[h*HID+tid+256];
    #pragma unroll
    for (int rr=0;rr<8;++rr){
      float x = xs[rr][h];
      aq[rr] += x*wq; ak[rr] += x*wk; av0[rr] += x*wv0; av1[rr] += x*wv1;
    }
  }
  #pragma unroll
  for (int rr=0;rr<8;++rr){
    g_q[(r0+rr)*RD+tid]  = aq[rr]+bq[tid];
    g_k[(r0+rr)*RD+tid]  = ak[rr]+bk[tid];
    g_v[(r0+rr)*HID+tid]      = av0[rr]+bv[tid];
    g_v[(r0+rr)*HID+tid+256]  = av1[rr]+bv[tid+256];
  }
}

// ---------------- kernel B: pair-MLP; og-private arenas + og-scoped barriers ----------------
#define NTB 512
__global__ void __launch_bounds__(512) kB(
    const float* __restrict__ edge, const float* __restrict__ lrel_in,
    const int* __restrict__ drctn, const float* __restrict__ rmask,
    const float* __restrict__ ln1g, const float* __restrict__ ln1b,
    const float* __restrict__ W1, const float* __restrict__ b1,
    const float* __restrict__ ln2g, const float* __restrict__ ln2b,
    const float* __restrict__ W2, const float* __restrict__ b2,
    const float* __restrict__ dirW,
    const float* __restrict__ ln3g, const float* __restrict__ ln3b,
    const float* __restrict__ W3, const float* __restrict__ b3,
    float* __restrict__ lrel_out)
{
  extern __shared__ float sm[];
  float* W1s = sm;                 // 32768
  float* W2s = W1s + 32768;        // 8192
  float* W3s = W2s + 8192;         // 512
  float* dirs = W3s + 512;         // 768
  float* l1g = dirs + 768;         // 256
  float* l1b = l1g + 256;          // 256
  float* b1s = l1b + 256;          // 128
  float* l2g = b1s + 128;          // 128
  float* l2b = l2g + 128;          // 128
  float* b2s = l2b + 128;          // 64
  float* l3g = b2s + 64;           // 64
  float* l3b = l3g + 64;           // 64
  float* b3s = l3b + 64;           // 8
  float* qs  = b3s + 8;            // 256
  int*   dj  = (int*)(qs + 256);   // 64 (32 used)
  float* rel = (float*)(dj + 64);  // 8192 : rows + og-private arenas rel[og*2048..]
  float* h1  = rel + 8192;         // 4096
  float* a3s = h1 + 4096;          // 2080 (dedicated, stride-65)
  // total 58024 floats = 232096 B (<= 232448)

  int tid = threadIdx.x;
  for (int i=tid; i<32768; i+=NTB) W1s[i]=W1[i];
  for (int i=tid; i<8192;  i+=NTB) W2s[i]=W2[i];
  for (int i=tid; i<512;   i+=NTB) W3s[i]=W3[i];
  for (int i=tid; i<768;   i+=NTB) dirs[i]=dirW[i];
  if (tid<256){ l1g[tid]=ln1g[tid]; l1b[tid]=ln1b[tid]; }
  if (tid<128){ b1s[tid]=b1[tid]; l2g[tid]=ln2g[tid]; l2b[tid]=ln2b[tid]; }
  if (tid<64){  b2s[tid]=b2[tid]; l3g[tid]=ln3g[tid]; l3b[tid]=ln3b[tid]; }
  if (tid<8)    b3s[tid]=b3[tid];

  int w = tid>>5, lane = tid&31;
  int og = w>>2, ks = w&3;             // 4 output groups x 4 K-splits

  for (int tl = blockIdx.x; tl < TILES; tl += gridDim.x){
    int bi = tl/(NN/TJ);
    int j0 = (tl%(NN/TJ))*TJ;
    int brow = (bi/NN)*NN;

    // stage tile params + prefetch DRAM operands (regs / regions idle since prior fulls)
    if (tid<256) qs[tid] = g_q[bi*RD+tid];
    if (tid<TJ) dj[tid] = drctn[(size_t)bi*NN + j0 + tid];
    float2 lrin_pf[8];
    if (ks==0){
      #pragma unroll
      for (int p=0;p<8;++p){
        size_t base = ((size_t)bi*NN + j0 + 8*og + p)*R4 + 2*lane;
        lrin_pf[p] = *(const float2*)(lrel_in + base);
      }
    }
    float rm_pf = 0.f;
    size_t ib_pf = 0;
    if (tid < 256){
      int t = tid>>3, hh = tid&7;
      ib_pf = ((size_t)bi*NN + j0 + t)*NH + hh;
      rm_pf = rmask[ib_pf];
    }
    __syncthreads();                   // FULL (1): prior epilogue p3 reads done; qs/dj visible

    // phase 1: rel = q_i * k_j + edge + dir_emb[d]   (cross-og writes)
    {
      int half = tid>>8, c = tid&255;
      float qv = qs[c];
      const float* kp = g_k + (size_t)(brow + j0 + half*16)*RD + c;
      const float* ep = edge + ((size_t)bi*NN + j0 + half*16)*RD + c;
      float* rp = rel + (half*16)*RD + c;
      #pragma unroll 4
      for (int t0=0;t0<16;++t0){
        float kv = kp[(size_t)t0*RD];
        float ev = ep[(size_t)t0*RD];
        float dv = dirs[dj[half*16+t0]*RD + c];
        rp[t0*RD] = qv*kv + ev + dv;
      }
    }
    __syncthreads();                   // FULL (3): rel ready for all ogs

    // ------- og-independent span begins: all buffers og-private -------
    float* arena = rel + og*2048;      // og's 2048-float private arena (its own 8 rows)

    // LN1 fused: warp w owns pairs 2w, 2w+1 (rows within own og)
    #pragma unroll
    for (int p=0;p<2;++p){
      int t = 2*w+p;
      float v[8]; float s=0.f,q2=0.f;
      #pragma unroll
      for (int u=0;u<8;++u){ v[u] = rel[t*RD + lane+32*u]; s+=v[u]; q2+=v[u]*v[u]; }
      s=warp_sum(s); q2=warp_sum(q2);
      float m = s*(1.f/RD);
      float rstd = rsqrtf(q2*(1.f/RD)-m*m+1e-5f);
      #pragma unroll
      for (int u=0;u<8;++u){
        int r = lane+32*u;
        rel[t*RD + r] = (v[u]-m)*rstd*l1g[r]+l1b[r];
      }
    }
    BAR_OG();                          // (4)

    // GEMM1: h1 = relu(LNrel @ W1 + b1). warp tile = 8 pairs x 128 cols, 4-way split-K.
    {
      ull acc[8][2];
      #pragma unroll
      for (int p=0;p<8;++p){ acc[p][0]=0ull; acc[p][1]=0ull; }
      const int rbase = ks*64;
      const float* rp = rel + (8*og)*RD;
      #pragma unroll 2
      for (int rb=rbase; rb<rbase+64; rb+=4){
        float a4[8][4];
        #pragma unroll
        for (int p=0;p<8;++p) *(float4*)a4[p] = *(const float4*)(rp + p*RD + rb);
        #pragma unroll
        for (int k=0;k<4;++k){
          ulonglong2 wv = *(const ulonglong2*)(W1s + (rb+k)*R2 + 4*lane);
          #pragma unroll
          for (int p=0;p<8;++p){
            ull a = pack2(a4[p][k]);
            acc[p][0] = fma2(a, wv.x, acc[p][0]);
            acc[p][1] = fma2(a, wv.y, acc[p][1]);
          }
        }
      }
      BAR_OG();                        // (5) og's 4 warps done reading own rel rows
      // publish partials into og-private space: ks1/ks2 -> arena, ks3 -> h1[og*1024..]
      if (ks==1){
        #pragma unroll
        for (int p=0;p<8;++p){ ulonglong2 v; v.x=acc[p][0]; v.y=acc[p][1];
          *(ulonglong2*)(arena + p*128 + 4*lane) = v; }
      } else if (ks==2){
        #pragma unroll
        for (int p=0;p<8;++p){ ulonglong2 v; v.x=acc[p][0]; v.y=acc[p][1];
          *(ulonglong2*)(arena + 1024 + p*128 + 4*lane) = v; }
      } else if (ks==3){
        #pragma unroll
        for (int p=0;p<8;++p){ ulonglong2 v; v.x=acc[p][0]; v.y=acc[p][1];
          *(ulonglong2*)(h1 + og*1024 + p*128 + 4*lane) = v; }
      }
      BAR_OG();                        // (6)
      if (ks==0){
        int c0=4*lane;
        #pragma unroll
        for (int p=0;p<8;++p){
          float4 q1 = *(const float4*)(arena + p*128 + c0);
          float4 q2 = *(const float4*)(arena + 1024 + p*128 + c0);
          float4 q3 = *(const float4*)(h1 + og*1024 + p*128 + c0);
          float4 o;
          o.x=fmaxf(lo2(acc[p][0])+q1.x+q2.x+q3.x+b1s[c0  ],0.f);
          o.y=fmaxf(hi2(acc[p][0])+q1.y+q2.y+q3.y+b1s[c0+1],0.f);
          o.z=fmaxf(lo2(acc[p][1])+q1.z+q2.z+q3.z+b1s[c0+2],0.f);
          o.w=fmaxf(hi2(acc[p][1])+q1.w+q2.w+q3.w+b1s[c0+3],0.f);
          *(float4*)(h1 + (8*og+p)*R2 + c0) = o;
        }
      }
    }
    BAR_OG();                          // (7) h1 rows for this og ready

    // LN2 fused: warp w owns pairs 2w, 2w+1 (own og rows)
    #pragma unroll
    for (int p=0;p<2;++p){
      int t=2*w+p;
      float v[4]; float s=0.f,q2=0.f;
      #pragma unroll
      for (int u=0;u<4;++u){ v[u]=h1[t*R2+lane+32*u]; s+=v[u]; q2+=v[u]*v[u]; }
      s=warp_sum(s); q2=warp_sum(q2);
      float m = s*(1.f/R2);
      float rstd = rsqrtf(q2*(1.f/R2)-m*m+1e-5f);
      #pragma unroll
      for (int u=0;u<4;++u){
        int r = lane+32*u;
        h1[t*R2+r]=(v[u]-m)*rstd*l2g[r]+l2b[r];
      }
    }
    BAR_OG();                          // (8)

    // GEMM2 + add last_relation; warp tile = 8 pairs x 64 cols, 4-way split-K.
    // partials + lr all inside og's arena (rel rows are dead for this og now)
    float* lrog = arena + 1536;        // 512 floats: og's last_rel tile rows
    {
      ull acc[8];
      #pragma unroll
      for (int p=0;p<8;++p) acc[p]=0ull;
      const int rbase = ks*32;
      const float* hp = h1 + (8*og)*R2;
      #pragma unroll 2
      for (int rb=rbase; rb<rbase+32; rb+=4){
        float a4[8][4];
        #pragma unroll
        for (int p=0;p<8;++p) *(float4*)a4[p] = *(const float4*)(hp + p*R2 + rb);
        #pragma unroll
        for (int k=0;k<4;++k){
          ull wv = *(const ull*)(W2s + (rb+k)*R4 + 2*lane);
          #pragma unroll
          for (int p=0;p<8;++p) acc[p] = fma2(pack2(a4[p][k]), wv, acc[p]);
        }
      }
      // publish immediately (targets disjoint from h1 reads; og-internal order via prior bars)
      if (ks==1){
        #pragma unroll
        for (int p=0;p<8;++p) *(ull*)(arena + p*64 + 2*lane) = acc[p];
      } else if (ks==2){
        #pragma unroll
        for (int p=0;p<8;++p) *(ull*)(arena + 512 + p*64 + 2*lane) = acc[p];
      } else if (ks==3){
        #pragma unroll
        for (int p=0;p<8;++p) *(ull*)(arena + 1024 + p*64 + 2*lane) = acc[p];
      }
      BAR_OG();                        // (10)
      if (ks==0){
        int c0=2*lane;
        #pragma unroll
        for (int p=0;p<8;++p){
          int t=8*og+p;
          ull q1 = *(const ull*)(arena + p*64 + c0);
          ull q2 = *(const ull*)(arena + 512 + p*64 + c0);
          ull q3 = *(const ull*)(arena + 1024 + p*64 + c0);
          size_t base = ((size_t)bi*NN + j0 + t)*R4 + c0;
          float2 o;
          o.x = lo2(acc[p])+lo2(q1)+lo2(q2)+lo2(q3)+b2s[c0  ]+lrin_pf[p].x;
          o.y = hi2(acc[p])+hi2(q1)+hi2(q2)+hi2(q3)+b2s[c0+1]+lrin_pf[p].y;
          *(float2*)(lrel_out + base) = o;
          lrog[p*64+c0]=o.x; lrog[p*64+c0+1]=o.y;
        }
      }
    }
    BAR_OG();                          // (11) og's lr ready

    // LN3 fused on relu(last_rel): warp w owns pairs 2w,2w+1; writes dedicated a3s
    #pragma unroll
    for (int p=0;p<2;++p){
      int t=2*w+p;
      int pl = t - 8*og;               // local row in lrog
      float v0=fmaxf(lrog[pl*64+lane],0.f), v1=fmaxf(lrog[pl*64+lane+32],0.f);
      float s=warp_sum(v0+v1), q2=warp_sum(v0*v0+v1*v1);
      float m = s*(1.f/R4);
      float rstd = rsqrtf(q2*(1.f/R4)-m*m+1e-5f);
      a3s[t*65+lane]    = (v0-m)*rstd*l3g[lane]+l3b[lane];
      a3s[t*65+lane+32] = (v1-m)*rstd*l3g[lane+32]+l3b[lane+32];
    }
    __syncthreads();                   // FULL (12): a3 is read cross-og

    // GEMM3 partials: warp w covers k in [4w,4w+4), lane = pair; conflict-free
    ull* p3 = (ull*)(rel + 4096);      // 4 head-pair regions x 512 ull (arenas dead)
    {
      ull acc0=0,acc1=0,acc2=0,acc3=0;
      #pragma unroll
      for (int u=0;u<4;++u){
        int k = w*4+u;
        ull a2 = pack2(a3s[lane*65 + k]);
        ulonglong2 w01 = *(const ulonglong2*)(W3s + k*NH);
        ulonglong2 w23 = *(const ulonglong2*)(W3s + k*NH + 4);
        acc0=fma2(a2,w01.x,acc0); acc1=fma2(a2,w01.y,acc1);
        acc2=fma2(a2,w23.x,acc2); acc3=fma2(a2,w23.y,acc3);
      }
      p3[0*512 + w*32 + lane]=acc0;    // heads 0,1
      p3[1*512 + w*32 + lane]=acc1;    // heads 2,3
      p3[2*512 + w*32 + lane]=acc2;    // heads 4,5
      p3[3*512 + w*32 + lane]=acc3;    // heads 6,7
    }
    __syncthreads();                   // FULL (13)
    if (tid < 256){
      int t = tid>>3, hh = tid&7;
      const float* scrf = rel + 4096;
      float acc=0.f;
      #pragma unroll
      for (int u=0;u<16;++u) acc += scrf[(hh>>1)*1024 + (u*32+t)*2 + (hh&1)];
      g_att[ib_pf] = acc + b3s[hh] + rm_pf;
    }
  }
}

// ---------------- kernel C: softmax over j ----------------
__global__ void __launch_bounds__(256) kC()
{
  __shared__ float s[NN*NH];
  int bi = blockIdx.x, tid=threadIdx.x;
  float* g = g_att + (size_t)bi*NN*NH;
  for (int i=tid;i<NN*NH;i+=256) s[i]=g[i];
  __syncthreads();
  int w=tid>>5, lane=tid&31;
  float mx=-3.4e38f;
  float e[12];
  #pragma unroll
  for (int u=0;u<12;++u) mx = fmaxf(mx, s[(lane+32*u)*NH + w]);
  #pragma unroll
  for (int o=16;o;o>>=1) mx = fmaxf(mx, __shfl_xor_sync(0xffffffffu,mx,o));
  float sum=0.f;
  #pragma unroll
  for (int u=0;u<12;++u){ e[u]=__expf(s[(lane+32*u)*NH+w]-mx); sum+=e[u]; }
  sum = warp_sum(sum);
  float inv = 1.f/sum;
  #pragma unroll
  for (int u=0;u<12;++u) s[(lane+32*u)*NH+w] = e[u]*inv;
  __syncthreads();
  for (int i=tid;i<NN*NH;i+=256) g[i]=s[i];
}

// ---------------- kernel D: partial attn*V over j-splits ----------------
__global__ void __launch_bounds__(256) kD()
{
  __shared__ float as[4][32*NH];
  int tid=threadIdx.x;
  int row0 = blockIdx.x*4;
  int js = blockIdx.y;
  int b = row0/NN;
  int h0 = tid>>6;
  float acc0[4], acc1[4];
  #pragma unroll
  for (int rr=0;rr<4;++rr){acc0[rr]=0.f;acc1[rr]=0.f;}
  for (int jc=0;jc<3;++jc){
    int jb = js*96 + jc*32;
    __syncthreads();
    for (int idx=tid; idx<4*32*NH; idx+=256){
      int rr=idx>>8, rest=idx&255;
      as[rr][rest] = g_att[((size_t)(row0+rr)*NN + jb)*NH + rest];
    }
    __syncthreads();
    #pragma unroll 4
    for (int jj=0;jj<32;++jj){
      const float* vp = g_v + (size_t)(b*NN + jb+jj)*HID;
      float v0=vp[tid], v1=vp[tid+256];
      #pragma unroll
      for (int rr=0;rr<4;++rr){
        acc0[rr]+=as[rr][jj*NH+h0]*v0;
        acc1[rr]+=as[rr][jj*NH+h0+4]*v1;
      }
    }
  }
  #pragma unroll
  for (int rr=0;rr<4;++rr){
    g_out1p[js][(row0+rr)*HID + tid]     = acc0[rr];
    g_out1p[js][(row0+rr)*HID + tid+256] = acc1[rr];
  }
}

// ---------------- kernel E ----------------
__global__ void __launch_bounds__(256) kE(const float* __restrict__ Wo,
                                          const float* __restrict__ bo,
                                          float* __restrict__ out)
{
  __shared__ float ys[8][HID];
  int tid=threadIdx.x; int r0=blockIdx.x*8;
  for (int idx=tid; idx<8*HID; idx+=256){
    size_t base=(size_t)r0*HID+idx;
    ys[idx>>9][idx&511] = g_out1p[0][base]+g_out1p[1][base]+g_out1p[2][base]+g_out1p[3][base];
  }
  __syncthreads();
  float a0[8],a1[8];
  #pragma unroll
  for (int rr=0;rr<8;++rr){a0[rr]=0.f;a1[rr]=0.f;}
  #pragma unroll 4
  for (int h=0;h<HID;++h){
    float w0=Wo[h*HID+tid], w1=Wo[h*HID+tid+256];
    #pragma unroll
    for (int rr=0;rr<8;++rr){ float x=ys[rr][h]; a0[rr]+=x*w0; a1[rr]+=x*w1; }
  }
  #pragma unroll
  for (int rr=0;rr<8;++rr){
    out[(r0+rr)*HID+tid]     = a0[rr]+bo[tid];
    out[(r0+rr)*HID+tid+256] = a1[rr]+bo[tid+256];
  }
}

// ---------------- launch ----------------
extern "C" void kernel_launch(void* const* d_in, const int* in_sizes, int n_in,
                              void* d_out, int out_size)
{
  const float* node        = (const float*)d_in[0];
  const float* edge        = (const float*)d_in[1];
  const float* last_rel_in = (const float*)d_in[2];
  const int* drctn         = (const int*)d_in[3];
  const float* rel_mask    = (const float*)d_in[4];
  const float* ln0_g=(const float*)d_in[5];  const float* ln0_b=(const float*)d_in[6];
  const float* Wq=(const float*)d_in[7];     const float* bq=(const float*)d_in[8];
  const float* Wk=(const float*)d_in[9];     const float* bk=(const float*)d_in[10];
  const float* Wv=(const float*)d_in[11];    const float* bv=(const float*)d_in[12];
  const float* ln1_g=(const float*)d_in[13]; const float* ln1_b=(const float*)d_in[14];
  const float* W1=(const float*)d_in[15];    const float* b1=(const float*)d_in[16];
  const float* ln2_g=(const float*)d_in[17]; const float* ln2_b=(const float*)d_in[18];
  const float* W2=(const float*)d_in[19];    const float* b2=(const float*)d_in[20];
  const float* dir_emb=(const float*)d_in[21];
  const float* ln3_g=(const float*)d_in[22]; const float* ln3_b=(const float*)d_in[23];
  const float* W3=(const float*)d_in[24];    const float* b3=(const float*)d_in[25];
  const float* Wo=(const float*)d_in[26];    const float* bo=(const float*)d_in[27];

  float* out = (float*)d_out;
  const size_t LRELN = (size_t)BB*NN*NN*R4;
  float* lrel_out = out + ((size_t)out_size - LRELN);

  kNop<<<1,32>>>();
  kNop<<<1,32>>>();

  kA<<<ROWS/8,256>>>(node, ln0_g, ln0_b, Wq,bq,Wk,bk,Wv,bv);

  const int SMEM_B = 58024*4;   // 232096 bytes
  cudaFuncSetAttribute(kB, cudaFuncAttributeMaxDynamicSharedMemorySize, SMEM_B);
  kB<<<152,512,SMEM_B>>>(edge, last_rel_in, drctn, rel_mask,
                         ln1_g, ln1_b, W1, b1, ln2_g, ln2_b, W2, b2,
                         dir_emb, ln3_g, ln3_b, W3, b3, lrel_out);

  kC<<<ROWS,256>>>();
  kD<<<dim3(192,4),256>>>();
  kE<<<ROWS/8,256>>>(Wo, bo, out);
}